// round 1
// baseline (speedup 1.0000x reference)
#include <cuda_runtime.h>
#include <math.h>

#define N_NODES 8192
#define F_IN    512
#define F_OUT   64
#define ALPHA   0.2f
#define MASK_VAL -9000000000000000.0f

// Scratch (no allocations allowed in kernel_launch)
__device__ float g_Wh[N_NODES * F_OUT];
__device__ float g_s1[N_NODES];
__device__ float g_s2[N_NODES];

// ---------------------------------------------------------------------------
// Kernel A: Wh = x @ W    (8192x512 @ 512x64)
// Block computes 64 rows x 64 cols; thread: 4 rows x 4 cols register tile.
// ---------------------------------------------------------------------------
__global__ __launch_bounds__(256) void wh_kernel(const float* __restrict__ x,
                                                 const float* __restrict__ W) {
    __shared__ float xs[64][65];   // padded: 2 rows/warp -> distinct banks
    __shared__ float ws[64 * 64];  // ws[cc][k], row stride 64 floats

    const int tid = threadIdx.x;
    const int r0  = blockIdx.x * 64;
    const int kq  = tid & 15;          // k quad: cols kq*4 .. kq*4+3
    const int rg  = tid >> 4;          // 16 row groups of 4 rows

    float acc[4][4] = {};

    for (int c0 = 0; c0 < F_IN; c0 += 64) {
        for (int idx = tid; idx < 64 * 64; idx += 256) {
            int row = idx >> 6, cc = idx & 63;
            xs[row][cc] = x[(r0 + row) * F_IN + c0 + cc];
        }
        for (int idx = tid; idx < 64 * 64; idx += 256) {
            int cc = idx >> 6, k = idx & 63;
            ws[cc * 64 + k] = W[(c0 + cc) * F_OUT + k];
        }
        __syncthreads();

        #pragma unroll 8
        for (int cc = 0; cc < 64; ++cc) {
            float4 wv = *(const float4*)&ws[cc * 64 + kq * 4];
            #pragma unroll
            for (int rr = 0; rr < 4; ++rr) {
                float xv = xs[rg * 4 + rr][cc];
                acc[rr][0] += xv * wv.x;
                acc[rr][1] += xv * wv.y;
                acc[rr][2] += xv * wv.z;
                acc[rr][3] += xv * wv.w;
            }
        }
        __syncthreads();
    }

    #pragma unroll
    for (int rr = 0; rr < 4; ++rr) {
        int row = r0 + rg * 4 + rr;
        float4 v = make_float4(acc[rr][0], acc[rr][1], acc[rr][2], acc[rr][3]);
        *(float4*)&g_Wh[row * F_OUT + kq * 4] = v;
    }
}

// ---------------------------------------------------------------------------
// Kernel B: s1 = Wh @ a1, s2 = Wh @ a2   (one warp per row)
// ---------------------------------------------------------------------------
__global__ __launch_bounds__(256) void s_kernel(const float* __restrict__ A) {
    const int row  = blockIdx.x * 8 + (threadIdx.x >> 5);
    const int lane = threadIdx.x & 31;
    float w0 = g_Wh[row * F_OUT + lane];
    float w1 = g_Wh[row * F_OUT + lane + 32];
    float v1 = w0 * A[lane]         + w1 * A[lane + 32];
    float v2 = w0 * A[F_OUT + lane] + w1 * A[F_OUT + lane + 32];
    #pragma unroll
    for (int off = 16; off; off >>= 1) {
        v1 += __shfl_xor_sync(0xFFFFFFFFu, v1, off);
        v2 += __shfl_xor_sync(0xFFFFFFFFu, v2, off);
    }
    if (lane == 0) { g_s1[row] = v1; g_s2[row] = v2; }
}

// ---------------------------------------------------------------------------
// Kernel C: fused mask + leaky_relu + online softmax + (attn @ Wh) + bias
// Block: 32 "i" rows, j tiled by 64.  256 threads.
// Accumulation mapping: kq = tid&15 (4 cols), rg = (tid>>4)&3 (8 rows),
// js = tid>>6 (4 j-slices, merged at end).
// ---------------------------------------------------------------------------
__global__ __launch_bounds__(256) void attn_kernel(const int* __restrict__ adj,
                                                   const float* __restrict__ bias,
                                                   float* __restrict__ out) {
    __shared__ float WhS[64 * 64];          // [j][k]  16 KB
    __shared__ float wS[32 * 65];           // padded row stride 65
    __shared__ float outS[32 * 64];
    __shared__ float s2S[64];
    __shared__ float s1S[32];
    __shared__ float mS[32], lS[32], fS[32];

    const int tid = threadIdx.x;
    const int i0  = blockIdx.x * 32;

    const int kq   = tid & 15;
    const int rg   = (tid >> 4) & 3;
    const int js   = tid >> 6;
    const int jj   = tid & 63;
    const int ib   = tid >> 6;       // 0..3 -> 8 rows each in e-phase
    const int row8 = tid >> 3;       // 0..31, softmax-state row
    const int p    = tid & 7;        // 8 threads per row

    if (tid < 32) {
        s1S[tid] = g_s1[i0 + tid];
        mS[tid]  = -INFINITY;
        lS[tid]  = 0.0f;
    }
    float acc[8][4] = {};
    __syncthreads();

    for (int jt = 0; jt < N_NODES / 64; ++jt) {
        const int j0 = jt * 64;

        // --- stage Wh[j0:j0+64][:] and s2 tile ---
        {
            const float4* whg  = (const float4*)&g_Wh[j0 * F_OUT];
            float4*       whs4 = (float4*)WhS;
            for (int idx = tid; idx < 64 * 16; idx += 256) whs4[idx] = whg[idx];
            if (tid < 64) s2S[tid] = g_s2[j0 + tid];
        }
        __syncthreads();

        // --- e tile: masked leaky_relu logits into wS ---
        #pragma unroll
        for (int r = 0; r < 8; ++r) {
            int il = ib * 8 + r;
            int a  = adj[(i0 + il) * N_NODES + j0 + jj];
            float t = s1S[il] + s2S[jj];
            float e = (a > 0) ? (t > 0.0f ? t : ALPHA * t) : MASK_VAL;
            wS[il * 65 + jj] = e;
        }
        __syncthreads();

        // --- per-row online softmax state update, e -> w in place ---
        {
            float tmax = -INFINITY;
            #pragma unroll
            for (int q = 0; q < 8; ++q)
                tmax = fmaxf(tmax, wS[row8 * 65 + p * 8 + q]);
            tmax = fmaxf(tmax, __shfl_xor_sync(0xFFFFFFFFu, tmax, 4));
            tmax = fmaxf(tmax, __shfl_xor_sync(0xFFFFFFFFu, tmax, 2));
            tmax = fmaxf(tmax, __shfl_xor_sync(0xFFFFFFFFu, tmax, 1));

            float mold = mS[row8];
            __syncwarp();
            float newm = fmaxf(mold, tmax);
            float fr   = __expf(mold - newm);

            float sum = 0.0f;
            #pragma unroll
            for (int q = 0; q < 8; ++q) {
                float w = __expf(wS[row8 * 65 + p * 8 + q] - newm);
                wS[row8 * 65 + p * 8 + q] = w;
                sum += w;
            }
            sum += __shfl_xor_sync(0xFFFFFFFFu, sum, 4);
            sum += __shfl_xor_sync(0xFFFFFFFFu, sum, 2);
            sum += __shfl_xor_sync(0xFFFFFFFFu, sum, 1);

            if (p == 0) {
                mS[row8] = newm;
                fS[row8] = fr;
                lS[row8] = lS[row8] * fr + sum;
            }
        }
        __syncthreads();

        // --- rescale accumulators, then accumulate w * Wh over this tile ---
        #pragma unroll
        for (int r = 0; r < 8; ++r) {
            float f = fS[rg * 8 + r];
            acc[r][0] *= f; acc[r][1] *= f; acc[r][2] *= f; acc[r][3] *= f;
        }
        {
            const float4* whs4 = (const float4*)WhS;
            #pragma unroll 4
            for (int q = 0; q < 16; ++q) {
                int j = js * 16 + q;
                float4 wh = whs4[j * 16 + kq];
                #pragma unroll
                for (int r = 0; r < 8; ++r) {
                    float wv = wS[(rg * 8 + r) * 65 + j];
                    acc[r][0] += wv * wh.x;
                    acc[r][1] += wv * wh.y;
                    acc[r][2] += wv * wh.z;
                    acc[r][3] += wv * wh.w;
                }
            }
        }
        __syncthreads();
    }

    // --- merge the 4 j-slices ---
    for (int idx = tid; idx < 32 * 64; idx += 256) outS[idx] = 0.0f;
    __syncthreads();
    for (int s = 0; s < 4; ++s) {
        if (js == s) {
            #pragma unroll
            for (int r = 0; r < 8; ++r) {
                float* o = &outS[(rg * 8 + r) * 64 + kq * 4];
                o[0] += acc[r][0]; o[1] += acc[r][1];
                o[2] += acc[r][2]; o[3] += acc[r][3];
            }
        }
        __syncthreads();
    }

    // --- normalize, add bias, store ---
    for (int idx = tid; idx < 32 * 64; idx += 256) {
        int il = idx >> 6, k = idx & 63;
        out[(i0 + il) * F_OUT + k] = outS[idx] / lS[il] + bias[k];
    }
}

// ---------------------------------------------------------------------------
extern "C" void kernel_launch(void* const* d_in, const int* in_sizes, int n_in,
                              void* d_out, int out_size) {
    const float* x    = (const float*)d_in[0];
    const int*   adj  = (const int*)  d_in[1];
    const float* W    = (const float*)d_in[2];
    const float* bias = (const float*)d_in[3];
    const float* A    = (const float*)d_in[4];
    float*       out  = (float*)d_out;

    wh_kernel  <<<N_NODES / 64, 256>>>(x, W);
    s_kernel   <<<N_NODES / 8,  256>>>(A);
    attn_kernel<<<N_NODES / 32, 256>>>(adj, bias, out);
}

// round 2
// speedup vs baseline: 1.1258x; 1.1258x over previous
#include <cuda_runtime.h>
#include <math.h>

#define N_NODES 8192
#define F_IN    512
#define F_OUT   64
#define ALPHA   0.2f

// Scratch (no allocations allowed in kernel_launch)
__device__ float g_Wh[N_NODES * F_OUT];
__device__ float g_s1[N_NODES];
__device__ float g_s2[N_NODES];
__device__ float g_s2max;

// ---- f32x2 helpers ---------------------------------------------------------
__device__ __forceinline__ unsigned long long pack2(float x) {
    unsigned long long d;
    asm("mov.b64 %0, {%1, %1};" : "=l"(d) : "r"(__float_as_uint(x)));
    return d;
}
__device__ __forceinline__ void ffma2(unsigned long long& d,
                                      unsigned long long a,
                                      unsigned long long b) {
    asm("fma.rn.f32x2 %0, %1, %2, %0;" : "+l"(d) : "l"(a), "l"(b));
}
union U64F2 { unsigned long long u; float f[2]; };

// ---------------------------------------------------------------------------
// Kernel A: Wh = x @ W  (8192x512 @ 512x64).  32 rows/block, grid 256.
// Thread: 2 rows x 4 cols (2 f32x2 accum per row).
// ---------------------------------------------------------------------------
__global__ __launch_bounds__(256) void wh_kernel(const float* __restrict__ x,
                                                 const float* __restrict__ W) {
    __shared__ __align__(16) float xs[32][65];
    __shared__ __align__(16) float ws[64 * 64];

    const int tid = threadIdx.x;
    const int r0  = blockIdx.x * 32;
    const int kq  = tid & 15;
    const int rg  = tid >> 4;          // 16 groups x 2 rows

    unsigned long long acc2[2][2] = {};

    for (int c0 = 0; c0 < F_IN; c0 += 64) {
        for (int idx = tid; idx < 32 * 64; idx += 256) {
            int row = idx >> 6, cc = idx & 63;
            xs[row][cc] = x[(r0 + row) * F_IN + c0 + cc];
        }
        {   // W chunk is contiguous: rows c0..c0+63 of [512][64]
            const float4* Wg4 = (const float4*)W;
            float4*       ws4 = (float4*)ws;
            for (int idx = tid; idx < 1024; idx += 256)
                ws4[idx] = Wg4[c0 * 16 + idx];
        }
        __syncthreads();

        #pragma unroll 8
        for (int cc = 0; cc < 64; ++cc) {
            ulonglong2 wv = *(const ulonglong2*)&ws[cc * 64 + kq * 4];
            unsigned long long x0 = pack2(xs[rg * 2 + 0][cc]);
            unsigned long long x1 = pack2(xs[rg * 2 + 1][cc]);
            ffma2(acc2[0][0], x0, wv.x); ffma2(acc2[0][1], x0, wv.y);
            ffma2(acc2[1][0], x1, wv.x); ffma2(acc2[1][1], x1, wv.y);
        }
        __syncthreads();
    }

    #pragma unroll
    for (int rr = 0; rr < 2; ++rr) {
        U64F2 a, b; a.u = acc2[rr][0]; b.u = acc2[rr][1];
        int row = r0 + rg * 2 + rr;
        float4 v = make_float4(a.f[0], a.f[1], b.f[0], b.f[1]);
        *(float4*)&g_Wh[row * F_OUT + kq * 4] = v;
    }
}

// ---------------------------------------------------------------------------
// Kernel B: s1 = Wh @ a1, s2 = Wh @ a2   (one warp per row)
// ---------------------------------------------------------------------------
__global__ __launch_bounds__(256) void s_kernel(const float* __restrict__ A) {
    const int row  = blockIdx.x * 8 + (threadIdx.x >> 5);
    const int lane = threadIdx.x & 31;
    float w0 = g_Wh[row * F_OUT + lane];
    float w1 = g_Wh[row * F_OUT + lane + 32];
    float v1 = w0 * A[lane]         + w1 * A[lane + 32];
    float v2 = w0 * A[F_OUT + lane] + w1 * A[F_OUT + lane + 32];
    #pragma unroll
    for (int off = 16; off; off >>= 1) {
        v1 += __shfl_xor_sync(0xFFFFFFFFu, v1, off);
        v2 += __shfl_xor_sync(0xFFFFFFFFu, v2, off);
    }
    if (lane == 0) { g_s1[row] = v1; g_s2[row] = v2; }
}

// ---------------------------------------------------------------------------
// Kernel B2: g_s2max = max(g_s2)  (single block)
// ---------------------------------------------------------------------------
__global__ __launch_bounds__(1024) void s2max_kernel() {
    __shared__ float sm[32];
    const int tid = threadIdx.x;
    float m = -INFINITY;
    for (int i = tid; i < N_NODES; i += 1024) m = fmaxf(m, g_s2[i]);
    #pragma unroll
    for (int off = 16; off; off >>= 1)
        m = fmaxf(m, __shfl_xor_sync(0xFFFFFFFFu, m, off));
    if ((tid & 31) == 0) sm[tid >> 5] = m;
    __syncthreads();
    if (tid < 32) {
        m = sm[tid];
        #pragma unroll
        for (int off = 16; off; off >>= 1)
            m = fmaxf(m, __shfl_xor_sync(0xFFFFFFFFu, m, off));
        if (tid == 0) g_s2max = m;
    }
}

// ---------------------------------------------------------------------------
// Kernel C: fused mask + leaky_relu + softmax(fixed upper-bound max) + attn@Wh
// Block: 32 i-rows, 256 threads, j tiled by 64.
//   kq = tid&15 (4 k cols), rg = (tid>>4)&3 (8 rows = 4 row-pairs), js = tid>>6
//   (4 j-slices of 16, merged at end).
// Weights stored TRANSPOSED: wT[j][row], pad 36 -> row-pair f32x2 loads.
// ---------------------------------------------------------------------------
__global__ __launch_bounds__(256) void attn_kernel(const int* __restrict__ adj,
                                                   const float* __restrict__ bias,
                                                   float* __restrict__ out) {
    __shared__ __align__(16) float WhS[64 * 64];   // [j][k]   16 KB
    __shared__ __align__(16) float wT[64 * 36];    // [j][row]  9 KB
    __shared__ float s2S[64];
    __shared__ float s1S[32], mS[32], lS[32];

    const int tid = threadIdx.x;
    const int i0  = blockIdx.x * 32;

    const int kq = tid & 15;
    const int rg = (tid >> 4) & 3;
    const int js = tid >> 6;
    const int jj = tid & 63;
    const int ib = tid >> 6;

    if (tid < 32) {
        float s1 = g_s1[i0 + tid];
        s1S[tid] = s1;
        float t = s1 + g_s2max;
        mS[tid] = (t > 0.0f) ? t : ALPHA * t;   // exact upper bound of row max
    }

    unsigned long long acc2[4][4] = {};   // [row-pair][k]
    float rsum[8] = {};

    for (int jt = 0; jt < N_NODES / 64; ++jt) {
        const int j0 = jt * 64;
        __syncthreads();   // previous accumulate done -> WhS/wT/s2S free

        {   // stage Wh tile + s2 tile
            const float4* whg  = (const float4*)&g_Wh[j0 * F_OUT];
            float4*       whs4 = (float4*)WhS;
            for (int idx = tid; idx < 64 * 16; idx += 256) whs4[idx] = whg[idx];
            if (tid < 64) s2S[tid] = g_s2[j0 + tid];
        }
        __syncthreads();

        // e-phase: w = adj ? exp(lrelu(s1+s2) - m) : 0  -> wT[j][row]
        const int* arow = adj + (size_t)(i0 + ib * 8) * N_NODES + j0 + jj;
        #pragma unroll
        for (int r = 0; r < 8; ++r) {
            int row = ib * 8 + r;
            int a   = arow[(size_t)r * N_NODES];
            float t = s1S[row] + s2S[jj];
            float e = (t > 0.0f) ? t : ALPHA * t;
            float w = (a > 0) ? __expf(e - mS[row]) : 0.0f;
            wT[jj * 36 + row] = w;
            rsum[r] += w;
        }
        __syncthreads();

        // accumulate: acc += w[j][rows] * Wh[j][k]
        #pragma unroll 4
        for (int q = 0; q < 16; ++q) {
            int j = js * 16 + q;
            ulonglong2 wp01 = *(const ulonglong2*)&wT[j * 36 + rg * 8];
            ulonglong2 wp23 = *(const ulonglong2*)&wT[j * 36 + rg * 8 + 4];
            float4 wh = *(const float4*)&WhS[j * 64 + kq * 4];
            unsigned long long h0 = pack2(wh.x), h1 = pack2(wh.y);
            unsigned long long h2 = pack2(wh.z), h3 = pack2(wh.w);
            ffma2(acc2[0][0], wp01.x, h0); ffma2(acc2[0][1], wp01.x, h1);
            ffma2(acc2[0][2], wp01.x, h2); ffma2(acc2[0][3], wp01.x, h3);
            ffma2(acc2[1][0], wp01.y, h0); ffma2(acc2[1][1], wp01.y, h1);
            ffma2(acc2[1][2], wp01.y, h2); ffma2(acc2[1][3], wp01.y, h3);
            ffma2(acc2[2][0], wp23.x, h0); ffma2(acc2[2][1], wp23.x, h1);
            ffma2(acc2[2][2], wp23.x, h2); ffma2(acc2[2][3], wp23.x, h3);
            ffma2(acc2[3][0], wp23.y, h0); ffma2(acc2[3][1], wp23.y, h1);
            ffma2(acc2[3][2], wp23.y, h2); ffma2(acc2[3][3], wp23.y, h3);
        }
    }
    __syncthreads();

    // row-sum reduction (reuse WhS, stride 65) + zero merge buffer (reuse wT)
    float* red  = WhS;
    float* outS = wT;
    #pragma unroll
    for (int r = 0; r < 8; ++r) red[(ib * 8 + r) * 65 + jj] = rsum[r];
    for (int idx = tid; idx < 32 * 64; idx += 256) outS[idx] = 0.0f;
    __syncthreads();

    if (tid < 32) {
        float s = 0.0f;
        for (int c = 0; c < 64; ++c) s += red[tid * 65 + c];
        lS[tid] = 1.0f / s;
    }

    // merge the 4 j-slices
    for (int s = 0; s < 4; ++s) {
        if (js == s) {
            #pragma unroll
            for (int p = 0; p < 4; ++p) {
                #pragma unroll
                for (int kk = 0; kk < 4; ++kk) {
                    U64F2 cv; cv.u = acc2[p][kk];
                    outS[(rg * 8 + 2 * p)     * 64 + kq * 4 + kk] += cv.f[0];
                    outS[(rg * 8 + 2 * p + 1) * 64 + kq * 4 + kk] += cv.f[1];
                }
            }
        }
        __syncthreads();
    }

    // normalize + bias + store
    for (int idx = tid; idx < 32 * 64; idx += 256) {
        int row = idx >> 6, k = idx & 63;
        out[(i0 + row) * F_OUT + k] = outS[idx] * lS[row] + bias[k];
    }
}

// ---------------------------------------------------------------------------
extern "C" void kernel_launch(void* const* d_in, const int* in_sizes, int n_in,
                              void* d_out, int out_size) {
    const float* x    = (const float*)d_in[0];
    const int*   adj  = (const int*)  d_in[1];
    const float* W    = (const float*)d_in[2];
    const float* bias = (const float*)d_in[3];
    const float* A    = (const float*)d_in[4];
    float*       out  = (float*)d_out;

    wh_kernel   <<<N_NODES / 32, 256>>>(x, W);
    s_kernel    <<<N_NODES / 8,  256>>>(A);
    s2max_kernel<<<1, 1024>>>();
    attn_kernel <<<N_NODES / 32, 256>>>(adj, bias, out);
}

// round 4
// speedup vs baseline: 1.4328x; 1.2727x over previous
#include <cuda_runtime.h>
#include <math.h>
#include <stdint.h>

#define N_NODES 8192
#define F_IN    512
#define F_OUT   64
#define ALPHA   0.2f

#define TJ      32
#define TILES   (N_NODES / TJ)     // 256
#define ROWS_B  64                 // i-rows per block

// SMEM stage layout (bytes)
#define ADJ_STRIDE 144             // 36 ints per adj row (32 data + pad)
#define WH_STRIDE  288             // 72 floats per Wh row (64 data + pad)
#define WH_OFF     9216            // after 64 adj rows
#define S2_OFF     18432
#define STAGE      18560
#define RING       4
#define LSUM_OFF   (STAGE * RING)  // 74240
#define SMEM_SZ    (LSUM_OFF + 256)

// Scratch (no allocations allowed anywhere)
__device__ float g_Wh [N_NODES * F_OUT];
__device__ float g_WhB[N_NODES * F_OUT];   // tf32-rounded copy for MMA B
__device__ float g_s1 [N_NODES];
__device__ float g_s2 [N_NODES];
__device__ float g_s2max;

// ---- helpers ---------------------------------------------------------------
__device__ __forceinline__ uint32_t smem_u32(const void* p) {
    uint32_t r;
    asm("{ .reg .u64 t; cvta.to.shared.u64 t, %1; cvt.u32.u64 %0, t; }"
        : "=r"(r) : "l"(p));
    return r;
}
__device__ __forceinline__ void cp_async16(uint32_t dst, const void* src) {
    asm volatile("cp.async.cg.shared.global [%0], [%1], 16;"
                 :: "r"(dst), "l"(src) : "memory");
}
__device__ __forceinline__ void cp_commit() {
    asm volatile("cp.async.commit_group;" ::: "memory");
}
__device__ __forceinline__ void cp_wait2() {
    asm volatile("cp.async.wait_group 2;" ::: "memory");
}
__device__ __forceinline__ uint32_t to_tf32(float x) {
    uint32_t r;
    asm("cvt.rna.tf32.f32 %0, %1;" : "=r"(r) : "f"(x));
    return r;
}

// ---- f32x2 helpers (wh kernel) --------------------------------------------
__device__ __forceinline__ unsigned long long pack2(float x) {
    unsigned long long d;
    asm("mov.b64 %0, {%1, %1};" : "=l"(d) : "r"(__float_as_uint(x)));
    return d;
}
__device__ __forceinline__ void ffma2(unsigned long long& d,
                                      unsigned long long a,
                                      unsigned long long b) {
    asm("fma.rn.f32x2 %0, %1, %2, %0;" : "+l"(d) : "l"(a), "l"(b));
}
union U64F2 { unsigned long long u; float f[2]; };

// ---------------------------------------------------------------------------
// Kernel A: Wh = x @ W  (exact fp32; also writes tf32-rounded copy g_WhB)
// ---------------------------------------------------------------------------
__global__ __launch_bounds__(256) void wh_kernel(const float* __restrict__ x,
                                                 const float* __restrict__ W) {
    __shared__ __align__(16) float xs[32][65];
    __shared__ __align__(16) float ws[64 * 64];

    const int tid = threadIdx.x;
    const int r0  = blockIdx.x * 32;
    const int kq  = tid & 15;
    const int rg  = tid >> 4;

    unsigned long long acc2[2][2] = {};

    for (int c0 = 0; c0 < F_IN; c0 += 64) {
        for (int idx = tid; idx < 32 * 64; idx += 256) {
            int row = idx >> 6, cc = idx & 63;
            xs[row][cc] = x[(r0 + row) * F_IN + c0 + cc];
        }
        {
            const float4* Wg4 = (const float4*)W;
            float4*       ws4 = (float4*)ws;
            for (int idx = tid; idx < 1024; idx += 256)
                ws4[idx] = Wg4[c0 * 16 + idx];
        }
        __syncthreads();

        #pragma unroll 8
        for (int cc = 0; cc < 64; ++cc) {
            ulonglong2 wv = *(const ulonglong2*)&ws[cc * 64 + kq * 4];
            unsigned long long x0 = pack2(xs[rg * 2 + 0][cc]);
            unsigned long long x1 = pack2(xs[rg * 2 + 1][cc]);
            ffma2(acc2[0][0], x0, wv.x); ffma2(acc2[0][1], x0, wv.y);
            ffma2(acc2[1][0], x1, wv.x); ffma2(acc2[1][1], x1, wv.y);
        }
        __syncthreads();
    }

    #pragma unroll
    for (int rr = 0; rr < 2; ++rr) {
        U64F2 a, b; a.u = acc2[rr][0]; b.u = acc2[rr][1];
        int row = r0 + rg * 2 + rr;
        float4 v = make_float4(a.f[0], a.f[1], b.f[0], b.f[1]);
        *(float4*)&g_Wh[row * F_OUT + kq * 4] = v;
        float4 vr;
        vr.x = __uint_as_float(to_tf32(v.x));
        vr.y = __uint_as_float(to_tf32(v.y));
        vr.z = __uint_as_float(to_tf32(v.z));
        vr.w = __uint_as_float(to_tf32(v.w));
        *(float4*)&g_WhB[row * F_OUT + kq * 4] = vr;
    }
}

// ---------------------------------------------------------------------------
// Kernel B: s1 = Wh @ a1, s2 = Wh @ a2
// ---------------------------------------------------------------------------
__global__ __launch_bounds__(256) void s_kernel(const float* __restrict__ A) {
    const int row  = blockIdx.x * 8 + (threadIdx.x >> 5);
    const int lane = threadIdx.x & 31;
    float w0 = g_Wh[row * F_OUT + lane];
    float w1 = g_Wh[row * F_OUT + lane + 32];
    float v1 = w0 * A[lane]         + w1 * A[lane + 32];
    float v2 = w0 * A[F_OUT + lane] + w1 * A[F_OUT + lane + 32];
    #pragma unroll
    for (int off = 16; off; off >>= 1) {
        v1 += __shfl_xor_sync(0xFFFFFFFFu, v1, off);
        v2 += __shfl_xor_sync(0xFFFFFFFFu, v2, off);
    }
    if (lane == 0) { g_s1[row] = v1; g_s2[row] = v2; }
}

// ---------------------------------------------------------------------------
// Kernel B2: g_s2max = max(g_s2)
// ---------------------------------------------------------------------------
__global__ __launch_bounds__(1024) void s2max_kernel() {
    __shared__ float sm[32];
    const int tid = threadIdx.x;
    float m = -INFINITY;
    for (int i = tid; i < N_NODES; i += 1024) m = fmaxf(m, g_s2[i]);
    #pragma unroll
    for (int off = 16; off; off >>= 1)
        m = fmaxf(m, __shfl_xor_sync(0xFFFFFFFFu, m, off));
    if ((tid & 31) == 0) sm[tid >> 5] = m;
    __syncthreads();
    if (tid < 32) {
        m = sm[tid];
        #pragma unroll
        for (int off = 16; off; off >>= 1)
            m = fmaxf(m, __shfl_xor_sync(0xFFFFFFFFu, m, off));
        if (tid == 0) g_s2max = m;
    }
}

// ---------------------------------------------------------------------------
// Kernel C: fused attention via mma.sync tf32 (m16n8k8).
// grid=128 (64 i-rows/block, full j range), 256 threads = 8 warps.
// Warp w: row-tile wr=w&3 (16 rows), col-half wc=w>>2 (32 of 64 f cols).
// Per 32-j tile: adj+WhB+s2 from cp.async ring (depth 4), A built in regs.
// ---------------------------------------------------------------------------
__global__ __launch_bounds__(256, 1) void attn_kernel(const int* __restrict__ adj,
                                                      const float* __restrict__ bias,
                                                      float* __restrict__ out) {
    extern __shared__ __align__(1024) char smem[];
    const int tid  = threadIdx.x;
    const int w    = tid >> 5, lane = tid & 31;
    const int wr   = w & 3,    wc   = w >> 2;
    const int g    = lane >> 2, tig = lane & 3;
    const int i0   = blockIdx.x * ROWS_B;
    const int r0l  = wr * 16 + g;
    const int r1l  = r0l + 8;

    float* lsumS = (float*)(smem + LSUM_OFF);
    const uint32_t sb = smem_u32(smem);

    // --- staged prefetch of one tile into ring slot t&3 ---
    auto prefetch = [&](int t) {
        if (t < TILES) {
            uint32_t base = sb + (t & 3) * STAGE;
            const int j0 = t * TJ;
            #pragma unroll
            for (int c = tid; c < 512; c += 256) {       // adj 64x32 ints
                int r = c >> 3, q = c & 7;
                cp_async16(base + r * ADJ_STRIDE + q * 16,
                           adj + (size_t)(i0 + r) * N_NODES + j0 + q * 4);
            }
            #pragma unroll
            for (int c = tid; c < 512; c += 256) {       // WhB 32x64 floats
                int r = c >> 4, q = c & 15;
                cp_async16(base + WH_OFF + r * WH_STRIDE + q * 16,
                           g_WhB + (j0 + r) * F_OUT + q * 4);
            }
            if (tid < 8)                                 // s2 32 floats
                cp_async16(base + S2_OFF + tid * 16, g_s2 + j0 + tid * 4);
        }
        cp_commit();
    };

    const float s1_0 = g_s1[i0 + r0l];
    const float s1_1 = g_s1[i0 + r1l];
    const float s2m  = g_s2max;
    float m0; { float t = s1_0 + s2m; m0 = t > 0.f ? t : ALPHA * t; }
    float m1; { float t = s1_1 + s2m; m1 = t > 0.f ? t : ALPHA * t; }

    float acc[4][4] = {};
    float sum0 = 0.f, sum1 = 0.f;

    prefetch(0); prefetch(1); prefetch(2);

    for (int t = 0; t < TILES; ++t) {
        cp_wait2();
        __syncthreads();
        prefetch(t + 3);     // refills slot (t-1)&3; reads of t-1 done pre-barrier

        const char*  base = smem + (t & 3) * STAGE;
        const float* s2p  = (const float*)(base + S2_OFF);
        const float* whp  = (const float*)(base + WH_OFF);

        // A fragments: 16 weights (2 rows x 8 j-cols), rounded to tf32
        uint32_t aw0[8], aw1[8];
        #pragma unroll
        for (int mm = 0; mm < 8; ++mm) {
            int j = tig + 4 * mm;
            float s2v = s2p[j];
            int a0 = *(const int*)(base + r0l * ADJ_STRIDE + j * 4);
            int a1 = *(const int*)(base + r1l * ADJ_STRIDE + j * 4);
            float e0 = s1_0 + s2v; e0 = e0 > 0.f ? e0 : ALPHA * e0;
            float e1 = s1_1 + s2v; e1 = e1 > 0.f ? e1 : ALPHA * e1;
            float w0 = (a0 > 0) ? __expf(e0 - m0) : 0.f;
            float w1 = (a1 > 0) ? __expf(e1 - m1) : 0.f;
            sum0 += w0; sum1 += w1;
            aw0[mm] = to_tf32(w0);
            aw1[mm] = to_tf32(w1);
        }

        #pragma unroll
        for (int k = 0; k < 4; ++k) {
            uint32_t a0 = aw0[2 * k],     a1 = aw1[2 * k];
            uint32_t a2 = aw0[2 * k + 1], a3 = aw1[2 * k + 1];
            #pragma unroll
            for (int n = 0; n < 4; ++n) {
                int f = wc * 32 + n * 8 + g;
                uint32_t b0 = __float_as_uint(whp[(k * 8 + tig)     * 72 + f]);
                uint32_t b1 = __float_as_uint(whp[(k * 8 + tig + 4) * 72 + f]);
                asm volatile(
                    "mma.sync.aligned.m16n8k8.row.col.f32.tf32.tf32.f32 "
                    "{%0,%1,%2,%3}, {%4,%5,%6,%7}, {%8,%9}, {%0,%1,%2,%3};"
                    : "+f"(acc[n][0]), "+f"(acc[n][1]),
                      "+f"(acc[n][2]), "+f"(acc[n][3])
                    : "r"(a0), "r"(a1), "r"(a2), "r"(a3), "r"(b0), "r"(b1));
            }
        }
    }

    // row sums (wc==0 warps own them; wc==1 computed duplicates)
    if (wc == 0) {
        sum0 += __shfl_xor_sync(0xFFFFFFFFu, sum0, 1);
        sum0 += __shfl_xor_sync(0xFFFFFFFFu, sum0, 2);
        sum1 += __shfl_xor_sync(0xFFFFFFFFu, sum1, 1);
        sum1 += __shfl_xor_sync(0xFFFFFFFFu, sum1, 2);
        if (tig == 0) { lsumS[r0l] = sum0; lsumS[r1l] = sum1; }
    }
    __syncthreads();

    const float inv0 = 1.0f / lsumS[r0l];
    const float inv1 = 1.0f / lsumS[r1l];

    #pragma unroll
    for (int n = 0; n < 4; ++n) {
        int f = wc * 32 + n * 8 + tig * 2;
        float2 bz = *(const float2*)&bias[f];
        float2 o0 = make_float2(acc[n][0] * inv0 + bz.x, acc[n][1] * inv0 + bz.y);
        float2 o1 = make_float2(acc[n][2] * inv1 + bz.x, acc[n][3] * inv1 + bz.y);
        *(float2*)&out[(size_t)(i0 + r0l) * F_OUT + f] = o0;
        *(float2*)&out[(size_t)(i0 + r1l) * F_OUT + f] = o1;
    }
}

// ---------------------------------------------------------------------------
extern "C" void kernel_launch(void* const* d_in, const int* in_sizes, int n_in,
                              void* d_out, int out_size) {
    const float* x    = (const float*)d_in[0];
    const int*   adj  = (const int*)  d_in[1];
    const float* W    = (const float*)d_in[2];
    const float* bias = (const float*)d_in[3];
    const float* A    = (const float*)d_in[4];
    float*       out  = (float*)d_out;

    static int smem_set = 0;
    if (!smem_set) {
        cudaFuncSetAttribute(attn_kernel,
                             cudaFuncAttributeMaxDynamicSharedMemorySize, SMEM_SZ);
        smem_set = 1;
    }

    wh_kernel   <<<N_NODES / 32, 256>>>(x, W);
    s_kernel    <<<N_NODES / 8,  256>>>(A);
    s2max_kernel<<<1, 1024>>>();
    attn_kernel <<<N_NODES / ROWS_B, 256, SMEM_SZ>>>(adj, bias, out);
}

// round 5
// speedup vs baseline: 2.1955x; 1.5323x over previous
#include <cuda_runtime.h>
#include <math.h>
#include <stdint.h>

#define N_NODES 8192
#define F_IN    512
#define F_OUT   64
#define ALPHA   0.2f

#define TJ      32
#define JSPLIT  4
#define JQ      (N_NODES / JSPLIT)   // 2048
#define TILES_B (JQ / TJ)            // 64 tiles per block
#define ROWS_B  64                   // i-rows per block

// SMEM stage layout (bytes)
#define ADJ_STRIDE 144               // 36 ints per adj row (32 data + pad)
#define WH_STRIDE  288               // 72 floats per Wh row (64 data + pad)
#define WH_OFF     9216              // after 64 adj rows
#define S2_OFF     18432
#define STAGE      18560
#define RING       4
#define SMEM_SZ    (STAGE * RING)    // 74240

// Scratch (no allocations allowed anywhere)
__device__ float g_Wh [N_NODES * F_OUT];
__device__ float g_WhB[N_NODES * F_OUT];   // tf32-rounded copy for MMA B
__device__ float g_s1 [N_NODES];
__device__ float g_s2 [N_NODES];
__device__ float g_s2max;
__device__ float g_part [JSPLIT][N_NODES * F_OUT];
__device__ float g_lpart[JSPLIT][N_NODES];

// ---- helpers ---------------------------------------------------------------
__device__ __forceinline__ uint32_t smem_u32(const void* p) {
    uint32_t r;
    asm("{ .reg .u64 t; cvta.to.shared.u64 t, %1; cvt.u32.u64 %0, t; }"
        : "=r"(r) : "l"(p));
    return r;
}
__device__ __forceinline__ void cp_async16(uint32_t dst, const void* src) {
    asm volatile("cp.async.cg.shared.global [%0], [%1], 16;"
                 :: "r"(dst), "l"(src) : "memory");
}
__device__ __forceinline__ void cp_commit() {
    asm volatile("cp.async.commit_group;" ::: "memory");
}
__device__ __forceinline__ void cp_wait2() {
    asm volatile("cp.async.wait_group 2;" ::: "memory");
}
__device__ __forceinline__ uint32_t to_tf32(float x) {
    uint32_t r;
    asm("cvt.rna.tf32.f32 %0, %1;" : "=r"(r) : "f"(x));
    return r;
}

// ---- f32x2 helpers (wh kernel) --------------------------------------------
__device__ __forceinline__ unsigned long long pack2(float x) {
    unsigned long long d;
    asm("mov.b64 %0, {%1, %1};" : "=l"(d) : "r"(__float_as_uint(x)));
    return d;
}
__device__ __forceinline__ void ffma2(unsigned long long& d,
                                      unsigned long long a,
                                      unsigned long long b) {
    asm("fma.rn.f32x2 %0, %1, %2, %0;" : "+l"(d) : "l"(a), "l"(b));
}
union U64F2 { unsigned long long u; float f[2]; };

// ---------------------------------------------------------------------------
// Kernel A: Wh = x @ W  (exact fp32; also writes tf32-rounded copy g_WhB)
// ---------------------------------------------------------------------------
__global__ __launch_bounds__(256) void wh_kernel(const float* __restrict__ x,
                                                 const float* __restrict__ W) {
    __shared__ __align__(16) float xs[32][65];
    __shared__ __align__(16) float ws[64 * 64];

    const int tid = threadIdx.x;
    const int r0  = blockIdx.x * 32;
    const int kq  = tid & 15;
    const int rg  = tid >> 4;

    unsigned long long acc2[2][2] = {};

    for (int c0 = 0; c0 < F_IN; c0 += 64) {
        for (int idx = tid; idx < 32 * 64; idx += 256) {
            int row = idx >> 6, cc = idx & 63;
            xs[row][cc] = x[(r0 + row) * F_IN + c0 + cc];
        }
        {
            const float4* Wg4 = (const float4*)W;
            float4*       ws4 = (float4*)ws;
            for (int idx = tid; idx < 1024; idx += 256)
                ws4[idx] = Wg4[c0 * 16 + idx];
        }
        __syncthreads();

        #pragma unroll 8
        for (int cc = 0; cc < 64; ++cc) {
            ulonglong2 wv = *(const ulonglong2*)&ws[cc * 64 + kq * 4];
            unsigned long long x0 = pack2(xs[rg * 2 + 0][cc]);
            unsigned long long x1 = pack2(xs[rg * 2 + 1][cc]);
            ffma2(acc2[0][0], x0, wv.x); ffma2(acc2[0][1], x0, wv.y);
            ffma2(acc2[1][0], x1, wv.x); ffma2(acc2[1][1], x1, wv.y);
        }
        __syncthreads();
    }

    #pragma unroll
    for (int rr = 0; rr < 2; ++rr) {
        U64F2 a, b; a.u = acc2[rr][0]; b.u = acc2[rr][1];
        int row = r0 + rg * 2 + rr;
        float4 v = make_float4(a.f[0], a.f[1], b.f[0], b.f[1]);
        *(float4*)&g_Wh[row * F_OUT + kq * 4] = v;
        float4 vr;
        vr.x = __uint_as_float(to_tf32(v.x));
        vr.y = __uint_as_float(to_tf32(v.y));
        vr.z = __uint_as_float(to_tf32(v.z));
        vr.w = __uint_as_float(to_tf32(v.w));
        *(float4*)&g_WhB[row * F_OUT + kq * 4] = vr;
    }
}

// ---------------------------------------------------------------------------
// Kernel B: s1 = Wh @ a1, s2 = Wh @ a2
// ---------------------------------------------------------------------------
__global__ __launch_bounds__(256) void s_kernel(const float* __restrict__ A) {
    const int row  = blockIdx.x * 8 + (threadIdx.x >> 5);
    const int lane = threadIdx.x & 31;
    float w0 = g_Wh[row * F_OUT + lane];
    float w1 = g_Wh[row * F_OUT + lane + 32];
    float v1 = w0 * A[lane]         + w1 * A[lane + 32];
    float v2 = w0 * A[F_OUT + lane] + w1 * A[F_OUT + lane + 32];
    #pragma unroll
    for (int off = 16; off; off >>= 1) {
        v1 += __shfl_xor_sync(0xFFFFFFFFu, v1, off);
        v2 += __shfl_xor_sync(0xFFFFFFFFu, v2, off);
    }
    if (lane == 0) { g_s1[row] = v1; g_s2[row] = v2; }
}

// ---------------------------------------------------------------------------
// Kernel B2: g_s2max = max(g_s2)
// ---------------------------------------------------------------------------
__global__ __launch_bounds__(1024) void s2max_kernel() {
    __shared__ float sm[32];
    const int tid = threadIdx.x;
    float m = -INFINITY;
    for (int i = tid; i < N_NODES; i += 1024) m = fmaxf(m, g_s2[i]);
    #pragma unroll
    for (int off = 16; off; off >>= 1)
        m = fmaxf(m, __shfl_xor_sync(0xFFFFFFFFu, m, off));
    if ((tid & 31) == 0) sm[tid >> 5] = m;
    __syncthreads();
    if (tid < 32) {
        m = sm[tid];
        #pragma unroll
        for (int off = 16; off; off >>= 1)
            m = fmaxf(m, __shfl_xor_sync(0xFFFFFFFFu, m, off));
        if (tid == 0) g_s2max = m;
    }
}

// ---------------------------------------------------------------------------
// Kernel C: fused attention via mma.sync tf32 (m16n8k8).
// grid = 128 i-blocks x 4 j-quarters = 512 blocks, 256 threads = 8 warps.
// Each block: 64 i-rows x 2048 j (64 tiles), writes UNNORMALIZED partials.
// Warp w: row-tile wr=w&3 (16 rows), col-half wc=w>>2 (32 of 64 f cols).
// ---------------------------------------------------------------------------
__global__ __launch_bounds__(256, 2) void attn_kernel(const int* __restrict__ adj) {
    extern __shared__ __align__(1024) char smem[];
    const int tid  = threadIdx.x;
    const int w    = tid >> 5, lane = tid & 31;
    const int wr   = w & 3,    wc   = w >> 2;
    const int g    = lane >> 2, tig = lane & 3;
    const int i0   = (blockIdx.x >> 2) * ROWS_B;
    const int qh   = blockIdx.x & 3;
    const int j0b  = qh * JQ;
    const int r0l  = wr * 16 + g;
    const int r1l  = r0l + 8;

    const uint32_t sb = smem_u32(smem);

    // --- staged prefetch of one tile into ring slot t&3 ---
    auto prefetch = [&](int t) {
        if (t < TILES_B) {
            uint32_t base = sb + (t & 3) * STAGE;
            const int j0 = j0b + t * TJ;
            #pragma unroll
            for (int c = tid; c < 512; c += 256) {       // adj 64x32 ints
                int r = c >> 3, q = c & 7;
                cp_async16(base + r * ADJ_STRIDE + q * 16,
                           adj + (size_t)(i0 + r) * N_NODES + j0 + q * 4);
            }
            #pragma unroll
            for (int c = tid; c < 512; c += 256) {       // WhB 32x64 floats
                int r = c >> 4, q = c & 15;
                cp_async16(base + WH_OFF + r * WH_STRIDE + q * 16,
                           g_WhB + (j0 + r) * F_OUT + q * 4);
            }
            if (tid < 8)                                 // s2 32 floats
                cp_async16(base + S2_OFF + tid * 16, g_s2 + j0 + tid * 4);
        }
        cp_commit();
    };

    const float s1_0 = g_s1[i0 + r0l];
    const float s1_1 = g_s1[i0 + r1l];
    const float s2m  = g_s2max;
    float m0; { float t = s1_0 + s2m; m0 = t > 0.f ? t : ALPHA * t; }
    float m1; { float t = s1_1 + s2m; m1 = t > 0.f ? t : ALPHA * t; }

    float acc[4][4] = {};
    float sum0 = 0.f, sum1 = 0.f;

    prefetch(0); prefetch(1); prefetch(2);

    for (int t = 0; t < TILES_B; ++t) {
        cp_wait2();
        __syncthreads();
        prefetch(t + 3);     // refills slot (t-1)&3; reads of t-1 done pre-barrier

        const char*  base = smem + (t & 3) * STAGE;
        const float* s2p  = (const float*)(base + S2_OFF);
        const float* whp  = (const float*)(base + WH_OFF);

        // A fragments: 16 weights (2 rows x 8 j-cols), rounded to tf32
        uint32_t aw0[8], aw1[8];
        #pragma unroll
        for (int mm = 0; mm < 8; ++mm) {
            int j = tig + 4 * mm;
            float s2v = s2p[j];
            int a0 = *(const int*)(base + r0l * ADJ_STRIDE + j * 4);
            int a1 = *(const int*)(base + r1l * ADJ_STRIDE + j * 4);
            float e0 = s1_0 + s2v; e0 = e0 > 0.f ? e0 : ALPHA * e0;
            float e1 = s1_1 + s2v; e1 = e1 > 0.f ? e1 : ALPHA * e1;
            float w0 = (a0 > 0) ? __expf(e0 - m0) : 0.f;
            float w1 = (a1 > 0) ? __expf(e1 - m1) : 0.f;
            sum0 += w0; sum1 += w1;
            aw0[mm] = to_tf32(w0);
            aw1[mm] = to_tf32(w1);
        }

        #pragma unroll
        for (int k = 0; k < 4; ++k) {
            uint32_t a0 = aw0[2 * k],     a1 = aw1[2 * k];
            uint32_t a2 = aw0[2 * k + 1], a3 = aw1[2 * k + 1];
            #pragma unroll
            for (int n = 0; n < 4; ++n) {
                int f = wc * 32 + n * 8 + g;
                uint32_t b0 = __float_as_uint(whp[(k * 8 + tig)     * 72 + f]);
                uint32_t b1 = __float_as_uint(whp[(k * 8 + tig + 4) * 72 + f]);
                asm volatile(
                    "mma.sync.aligned.m16n8k8.row.col.f32.tf32.tf32.f32 "
                    "{%0,%1,%2,%3}, {%4,%5,%6,%7}, {%8,%9}, {%0,%1,%2,%3};"
                    : "+f"(acc[n][0]), "+f"(acc[n][1]),
                      "+f"(acc[n][2]), "+f"(acc[n][3])
                    : "r"(a0), "r"(a1), "r"(a2), "r"(a3), "r"(b0), "r"(b1));
            }
        }
    }

    // partial row sums (wc==0 warps own them; wc==1 computed duplicates)
    if (wc == 0) {
        sum0 += __shfl_xor_sync(0xFFFFFFFFu, sum0, 1);
        sum0 += __shfl_xor_sync(0xFFFFFFFFu, sum0, 2);
        sum1 += __shfl_xor_sync(0xFFFFFFFFu, sum1, 1);
        sum1 += __shfl_xor_sync(0xFFFFFFFFu, sum1, 2);
        if (tig == 0) {
            g_lpart[qh][i0 + r0l] = sum0;
            g_lpart[qh][i0 + r1l] = sum1;
        }
    }

    // unnormalized partial outputs
    #pragma unroll
    for (int n = 0; n < 4; ++n) {
        int f = wc * 32 + n * 8 + tig * 2;
        *(float2*)&g_part[qh][(size_t)(i0 + r0l) * F_OUT + f] =
            make_float2(acc[n][0], acc[n][1]);
        *(float2*)&g_part[qh][(size_t)(i0 + r1l) * F_OUT + f] =
            make_float2(acc[n][2], acc[n][3]);
    }
}

// ---------------------------------------------------------------------------
// Kernel D: out = (sum_q part_q) / (sum_q l_q) + bias
// ---------------------------------------------------------------------------
__global__ __launch_bounds__(256) void combine_kernel(const float* __restrict__ bias,
                                                      float* __restrict__ out) {
    int idx = blockIdx.x * 256 + threadIdx.x;    // 8192*16 float4 slots
    int i  = idx >> 4;
    int fq = idx & 15;
    size_t off = (size_t)i * F_OUT + fq * 4;
    float4 p0 = *(const float4*)&g_part[0][off];
    float4 p1 = *(const float4*)&g_part[1][off];
    float4 p2 = *(const float4*)&g_part[2][off];
    float4 p3 = *(const float4*)&g_part[3][off];
    float inv = 1.0f / (g_lpart[0][i] + g_lpart[1][i] +
                        g_lpart[2][i] + g_lpart[3][i]);
    float4 bz = *(const float4*)&bias[fq * 4];
    float4 r;
    r.x = (p0.x + p1.x + p2.x + p3.x) * inv + bz.x;
    r.y = (p0.y + p1.y + p2.y + p3.y) * inv + bz.y;
    r.z = (p0.z + p1.z + p2.z + p3.z) * inv + bz.z;
    r.w = (p0.w + p1.w + p2.w + p3.w) * inv + bz.w;
    *(float4*)&out[off] = r;
}

// ---------------------------------------------------------------------------
extern "C" void kernel_launch(void* const* d_in, const int* in_sizes, int n_in,
                              void* d_out, int out_size) {
    const float* x    = (const float*)d_in[0];
    const int*   adj  = (const int*)  d_in[1];
    const float* W    = (const float*)d_in[2];
    const float* bias = (const float*)d_in[3];
    const float* A    = (const float*)d_in[4];
    float*       out  = (float*)d_out;

    cudaFuncSetAttribute(attn_kernel,
                         cudaFuncAttributeMaxDynamicSharedMemorySize, SMEM_SZ);

    wh_kernel   <<<N_NODES / 32, 256>>>(x, W);
    s_kernel    <<<N_NODES / 8,  256>>>(A);
    s2max_kernel<<<1, 1024>>>();
    attn_kernel <<<(N_NODES / ROWS_B) * JSPLIT, 256, SMEM_SZ>>>(adj);
    combine_kernel<<<N_NODES * 16 / 256, 256>>>(bias, out);
}

// round 6
// speedup vs baseline: 3.1773x; 1.4472x over previous
#include <cuda_runtime.h>
#include <math.h>
#include <stdint.h>

#define N_NODES 8192
#define F_IN    512
#define F_OUT   64
#define ALPHA   0.2f

#define TJ      32
#define JSPLIT  8
#define JQ      (N_NODES / JSPLIT)   // 1024
#define TILES_B (JQ / TJ)            // 32 tiles per block
#define ROWS_B  64                   // i-rows per block

// SMEM stage layout (bytes)
#define ADJ_STRIDE 144               // 36 ints per adj row (32 data + pad)
#define WH_STRIDE  288               // 72 floats per Wh row (64 data + pad)
#define WH_OFF     9216              // after 64 adj rows
#define S2_OFF     18432
#define STAGE      18560
#define RING       4
#define SMEM_SZ    (STAGE * RING)    // 74240 (x3 blocks = 222.7KB/SM)

// Scratch (no allocations allowed anywhere)
__device__ float g_Wh [N_NODES * F_OUT];
__device__ float g_WhB[N_NODES * F_OUT];   // tf32-rounded copy for MMA B
__device__ float g_s1 [N_NODES];
__device__ float g_s2 [N_NODES];
__device__ float g_s2max;
__device__ float g_part [JSPLIT][N_NODES * F_OUT];
__device__ float g_lpart[JSPLIT][N_NODES];

// ---- helpers ---------------------------------------------------------------
__device__ __forceinline__ uint32_t smem_u32(const void* p) {
    uint32_t r;
    asm("{ .reg .u64 t; cvta.to.shared.u64 t, %1; cvt.u32.u64 %0, t; }"
        : "=r"(r) : "l"(p));
    return r;
}
__device__ __forceinline__ void cp_async16(uint32_t dst, const void* src) {
    asm volatile("cp.async.cg.shared.global [%0], [%1], 16;"
                 :: "r"(dst), "l"(src) : "memory");
}
__device__ __forceinline__ void cp_commit() {
    asm volatile("cp.async.commit_group;" ::: "memory");
}
__device__ __forceinline__ void cp_wait1() {
    asm volatile("cp.async.wait_group 1;" ::: "memory");
}
__device__ __forceinline__ void cp_wait2() {
    asm volatile("cp.async.wait_group 2;" ::: "memory");
}
__device__ __forceinline__ uint32_t to_tf32(float x) {
    uint32_t r;
    asm("cvt.rna.tf32.f32 %0, %1;" : "=r"(r) : "f"(x));
    return r;
}
__device__ __forceinline__ void mma_tf32(float* c, uint32_t a0, uint32_t a1,
                                         uint32_t a2, uint32_t a3,
                                         uint32_t b0, uint32_t b1) {
    asm volatile(
        "mma.sync.aligned.m16n8k8.row.col.f32.tf32.tf32.f32 "
        "{%0,%1,%2,%3}, {%4,%5,%6,%7}, {%8,%9}, {%0,%1,%2,%3};"
        : "+f"(c[0]), "+f"(c[1]), "+f"(c[2]), "+f"(c[3])
        : "r"(a0), "r"(a1), "r"(a2), "r"(a3), "r"(b0), "r"(b1));
}

// ---------------------------------------------------------------------------
// Kernel A: Wh = x @ W via tf32 mma.sync. Block = 64 rows x 64 cols, K=512.
// 8 warps: wr=w&3 row-tile (16 rows), wc=w>>2 col-half (32 cols).
// Double-buffered cp.async staging of x (64x32) and W (32x64) per k-stage.
// ---------------------------------------------------------------------------
#define XS_STR 36
#define WS_STR 72
__global__ __launch_bounds__(256) void wh_kernel(const float* __restrict__ x,
                                                 const float* __restrict__ W) {
    __shared__ __align__(16) float xs[2][64 * XS_STR];
    __shared__ __align__(16) float ws[2][32 * WS_STR];

    const int tid  = threadIdx.x;
    const int w    = tid >> 5, lane = tid & 31;
    const int wr   = w & 3,    wc   = w >> 2;
    const int g    = lane >> 2, tig = lane & 3;
    const int r0   = blockIdx.x * 64;
    const int r0l  = wr * 16 + g;
    const int r1l  = r0l + 8;

    const uint32_t xs0 = smem_u32(xs);
    const uint32_t ws0 = smem_u32(ws);

    auto prefetch = [&](int s) {
        if (s < 16) {
            int b = s & 1;
            int k0 = s * 32;
            #pragma unroll
            for (int c = tid; c < 512; c += 256) {     // x: 64 rows x 32 k
                int r = c >> 3, q = c & 7;
                cp_async16(xs0 + (b * 64 * XS_STR + r * XS_STR) * 4 + q * 16,
                           x + (size_t)(r0 + r) * F_IN + k0 + q * 4);
            }
            #pragma unroll
            for (int c = tid; c < 512; c += 256) {     // W: 32 k x 64 f
                int r = c >> 4, q = c & 15;
                cp_async16(ws0 + (b * 32 * WS_STR + r * WS_STR) * 4 + q * 16,
                           W + (size_t)(k0 + r) * F_OUT + q * 4);
            }
        }
        cp_commit();
    };

    float acc[4][4] = {};
    prefetch(0);

    for (int s = 0; s < 16; ++s) {
        prefetch(s + 1);
        cp_wait1();
        __syncthreads();

        const float* xp = &xs[s & 1][0];
        const float* wp = &ws[s & 1][0];

        #pragma unroll
        for (int kc = 0; kc < 4; ++kc) {
            uint32_t a0 = to_tf32(xp[r0l * XS_STR + kc * 8 + tig]);
            uint32_t a1 = to_tf32(xp[r1l * XS_STR + kc * 8 + tig]);
            uint32_t a2 = to_tf32(xp[r0l * XS_STR + kc * 8 + tig + 4]);
            uint32_t a3 = to_tf32(xp[r1l * XS_STR + kc * 8 + tig + 4]);
            #pragma unroll
            for (int n = 0; n < 4; ++n) {
                int f = wc * 32 + n * 8 + g;
                uint32_t b0 = to_tf32(wp[(kc * 8 + tig)     * WS_STR + f]);
                uint32_t b1 = to_tf32(wp[(kc * 8 + tig + 4) * WS_STR + f]);
                mma_tf32(acc[n], a0, a1, a2, a3, b0, b1);
            }
        }
        __syncthreads();
    }

    #pragma unroll
    for (int n = 0; n < 4; ++n) {
        int f = wc * 32 + n * 8 + tig * 2;
        size_t o0 = (size_t)(r0 + r0l) * F_OUT + f;
        size_t o1 = (size_t)(r0 + r1l) * F_OUT + f;
        *(float2*)&g_Wh[o0] = make_float2(acc[n][0], acc[n][1]);
        *(float2*)&g_Wh[o1] = make_float2(acc[n][2], acc[n][3]);
        *(float2*)&g_WhB[o0] = make_float2(__uint_as_float(to_tf32(acc[n][0])),
                                           __uint_as_float(to_tf32(acc[n][1])));
        *(float2*)&g_WhB[o1] = make_float2(__uint_as_float(to_tf32(acc[n][2])),
                                           __uint_as_float(to_tf32(acc[n][3])));
    }
}

// ---------------------------------------------------------------------------
// Kernel B: s1 = Wh @ a1, s2 = Wh @ a2
// ---------------------------------------------------------------------------
__global__ __launch_bounds__(256) void s_kernel(const float* __restrict__ A) {
    const int row  = blockIdx.x * 8 + (threadIdx.x >> 5);
    const int lane = threadIdx.x & 31;
    float w0 = g_Wh[row * F_OUT + lane];
    float w1 = g_Wh[row * F_OUT + lane + 32];
    float v1 = w0 * A[lane]         + w1 * A[lane + 32];
    float v2 = w0 * A[F_OUT + lane] + w1 * A[F_OUT + lane + 32];
    #pragma unroll
    for (int off = 16; off; off >>= 1) {
        v1 += __shfl_xor_sync(0xFFFFFFFFu, v1, off);
        v2 += __shfl_xor_sync(0xFFFFFFFFu, v2, off);
    }
    if (lane == 0) { g_s1[row] = v1; g_s2[row] = v2; }
}

// ---------------------------------------------------------------------------
// Kernel B2: g_s2max = max(g_s2)
// ---------------------------------------------------------------------------
__global__ __launch_bounds__(1024) void s2max_kernel() {
    __shared__ float sm[32];
    const int tid = threadIdx.x;
    float m = -INFINITY;
    for (int i = tid; i < N_NODES; i += 1024) m = fmaxf(m, g_s2[i]);
    #pragma unroll
    for (int off = 16; off; off >>= 1)
        m = fmaxf(m, __shfl_xor_sync(0xFFFFFFFFu, m, off));
    if ((tid & 31) == 0) sm[tid >> 5] = m;
    __syncthreads();
    if (tid < 32) {
        m = sm[tid];
        #pragma unroll
        for (int off = 16; off; off >>= 1)
            m = fmaxf(m, __shfl_xor_sync(0xFFFFFFFFu, m, off));
        if (tid == 0) g_s2max = m;
    }
}

// ---------------------------------------------------------------------------
// Kernel C: fused attention via mma.sync tf32 (m16n8k8).
// grid = 128 i-blocks x 8 j-eighths = 1024 blocks, 256 threads = 8 warps.
// 3 blocks/SM. Each block: 64 i-rows x 1024 j (32 tiles), UNNORMALIZED out.
// ---------------------------------------------------------------------------
__global__ __launch_bounds__(256, 3) void attn_kernel(const int* __restrict__ adj) {
    extern __shared__ __align__(1024) char smem[];
    const int tid  = threadIdx.x;
    const int w    = tid >> 5, lane = tid & 31;
    const int wr   = w & 3,    wc   = w >> 2;
    const int g    = lane >> 2, tig = lane & 3;
    const int i0   = (blockIdx.x >> 3) * ROWS_B;
    const int qh   = blockIdx.x & 7;
    const int j0b  = qh * JQ;
    const int r0l  = wr * 16 + g;
    const int r1l  = r0l + 8;

    const uint32_t sb = smem_u32(smem);

    auto prefetch = [&](int t) {
        if (t < TILES_B) {
            uint32_t base = sb + (t & 3) * STAGE;
            const int j0 = j0b + t * TJ;
            #pragma unroll
            for (int c = tid; c < 512; c += 256) {       // adj 64x32 ints
                int r = c >> 3, q = c & 7;
                cp_async16(base + r * ADJ_STRIDE + q * 16,
                           adj + (size_t)(i0 + r) * N_NODES + j0 + q * 4);
            }
            #pragma unroll
            for (int c = tid; c < 512; c += 256) {       // WhB 32x64 floats
                int r = c >> 4, q = c & 15;
                cp_async16(base + WH_OFF + r * WH_STRIDE + q * 16,
                           g_WhB + (j0 + r) * F_OUT + q * 4);
            }
            if (tid < 8)                                 // s2 32 floats
                cp_async16(base + S2_OFF + tid * 16, g_s2 + j0 + tid * 4);
        }
        cp_commit();
    };

    const float s1_0 = g_s1[i0 + r0l];
    const float s1_1 = g_s1[i0 + r1l];
    const float s2m  = g_s2max;
    const float m0 = fmaxf(s1_0 + s2m, ALPHA * (s1_0 + s2m));
    const float m1 = fmaxf(s1_1 + s2m, ALPHA * (s1_1 + s2m));

    float acc[4][4] = {};
    float sum0 = 0.f, sum1 = 0.f;

    prefetch(0); prefetch(1); prefetch(2);

    for (int t = 0; t < TILES_B; ++t) {
        cp_wait2();
        __syncthreads();
        prefetch(t + 3);     // refills slot (t-1)&3; reads of t-1 done pre-barrier

        const char*  base = smem + (t & 3) * STAGE;
        const float* s2p  = (const float*)(base + S2_OFF);
        const float* whp  = (const float*)(base + WH_OFF);

        // A fragments: 16 weights (2 rows x 8 j-cols), rounded to tf32
        uint32_t aw0[8], aw1[8];
        #pragma unroll
        for (int mm = 0; mm < 8; ++mm) {
            int j = tig + 4 * mm;
            float s2v = s2p[j];
            int a0 = *(const int*)(base + r0l * ADJ_STRIDE + j * 4);
            int a1 = *(const int*)(base + r1l * ADJ_STRIDE + j * 4);
            float t0 = s1_0 + s2v;
            float t1 = s1_1 + s2v;
            float e0 = fmaxf(t0, ALPHA * t0);
            float e1 = fmaxf(t1, ALPHA * t1);
            float w0 = (a0 > 0) ? __expf(e0 - m0) : 0.f;
            float w1 = (a1 > 0) ? __expf(e1 - m1) : 0.f;
            sum0 += w0; sum1 += w1;
            aw0[mm] = to_tf32(w0);
            aw1[mm] = to_tf32(w1);
        }

        #pragma unroll
        for (int k = 0; k < 4; ++k) {
            uint32_t a0 = aw0[2 * k],     a1 = aw1[2 * k];
            uint32_t a2 = aw0[2 * k + 1], a3 = aw1[2 * k + 1];
            #pragma unroll
            for (int n = 0; n < 4; ++n) {
                int f = wc * 32 + n * 8 + g;
                uint32_t b0 = __float_as_uint(whp[(k * 8 + tig)     * 72 + f]);
                uint32_t b1 = __float_as_uint(whp[(k * 8 + tig + 4) * 72 + f]);
                mma_tf32(acc[n], a0, a1, a2, a3, b0, b1);
            }
        }
    }

    // partial row sums (wc==0 warps own them; wc==1 computed duplicates)
    if (wc == 0) {
        sum0 += __shfl_xor_sync(0xFFFFFFFFu, sum0, 1);
        sum0 += __shfl_xor_sync(0xFFFFFFFFu, sum0, 2);
        sum1 += __shfl_xor_sync(0xFFFFFFFFu, sum1, 1);
        sum1 += __shfl_xor_sync(0xFFFFFFFFu, sum1, 2);
        if (tig == 0) {
            g_lpart[qh][i0 + r0l] = sum0;
            g_lpart[qh][i0 + r1l] = sum1;
        }
    }

    // unnormalized partial outputs
    #pragma unroll
    for (int n = 0; n < 4; ++n) {
        int f = wc * 32 + n * 8 + tig * 2;
        *(float2*)&g_part[qh][(size_t)(i0 + r0l) * F_OUT + f] =
            make_float2(acc[n][0], acc[n][1]);
        *(float2*)&g_part[qh][(size_t)(i0 + r1l) * F_OUT + f] =
            make_float2(acc[n][2], acc[n][3]);
    }
}

// ---------------------------------------------------------------------------
// Kernel D: out = (sum_q part_q) / (sum_q l_q) + bias
// ---------------------------------------------------------------------------
__global__ __launch_bounds__(256) void combine_kernel(const float* __restrict__ bias,
                                                      float* __restrict__ out) {
    int idx = blockIdx.x * 256 + threadIdx.x;    // 8192*16 float4 slots
    int i  = idx >> 4;
    int fq = idx & 15;
    size_t off = (size_t)i * F_OUT + fq * 4;

    float4 p = *(const float4*)&g_part[0][off];
    float  l = g_lpart[0][i];
    #pragma unroll
    for (int q = 1; q < JSPLIT; ++q) {
        float4 pq = *(const float4*)&g_part[q][off];
        p.x += pq.x; p.y += pq.y; p.z += pq.z; p.w += pq.w;
        l += g_lpart[q][i];
    }
    float inv = 1.0f / l;
    float4 bz = *(const float4*)&bias[fq * 4];
    float4 r;
    r.x = p.x * inv + bz.x;
    r.y = p.y * inv + bz.y;
    r.z = p.z * inv + bz.z;
    r.w = p.w * inv + bz.w;
    *(float4*)&out[off] = r;
}

// ---------------------------------------------------------------------------
extern "C" void kernel_launch(void* const* d_in, const int* in_sizes, int n_in,
                              void* d_out, int out_size) {
    const float* x    = (const float*)d_in[0];
    const int*   adj  = (const int*)  d_in[1];
    const float* W    = (const float*)d_in[2];
    const float* bias = (const float*)d_in[3];
    const float* A    = (const float*)d_in[4];
    float*       out  = (float*)d_out;

    cudaFuncSetAttribute(attn_kernel,
                         cudaFuncAttributeMaxDynamicSharedMemorySize, SMEM_SZ);

    wh_kernel   <<<N_NODES / 64, 256>>>(x, W);
    s_kernel    <<<N_NODES / 8,  256>>>(A);
    s2max_kernel<<<1, 1024>>>();
    attn_kernel <<<(N_NODES / ROWS_B) * JSPLIT, 256, SMEM_SZ>>>(adj);
    combine_kernel<<<N_NODES * 16 / 256, 256>>>(bias, out);
}